// round 10
// baseline (speedup 1.0000x reference)
#include <cuda_runtime.h>
#include <cuda_fp16.h>
#include <cstdint>

#define MPTS 131072
#define BM 128
#define BN 128
#define BK 64                       // halves per k-chunk
#define STAGES 3
#define PITCH 72                    // smem row pitch in halves: 144B = 9*16B (odd) -> conflict-free
#define STAGE_F (128 * PITCH)       // halves per tile
#define SMEM_BYTES (STAGES * 2 * STAGE_F * 2)   // 110592 B

// ---- scratch (device globals; no allocation allowed) ----
__device__ __half g_h1[(size_t)MPTS * 256];
__device__ __half g_h2[(size_t)MPTS * 512];
__device__ __half g_w1t[256 * 256];           // W1[0:256]^T  [N][K] fp16
__device__ __half g_w2t[512 * 256];
__device__ __half g_w3t[1024 * 512];
__device__ float  g_w1tail[3 * 256];          // W1[256:259][:] fp32 (pos tail, rank-3)

// ---------------- helpers ----------------
__device__ __forceinline__ uint32_t s2u(const void* p) {
    uint32_t a;
    asm("{ .reg .u64 t; cvta.to.shared.u64 t, %1; cvt.u32.u64 %0, t; }" : "=r"(a) : "l"(p));
    return a;
}
__device__ __forceinline__ void cp16(uint32_t dst, const void* src) {
    asm volatile("cp.async.cg.shared.global [%0], [%1], 16;" :: "r"(dst), "l"(src));
}
__device__ __forceinline__ void ldsm4(uint32_t* r, uint32_t addr) {
    asm volatile("ldmatrix.sync.aligned.m8n8.x4.shared.b16 {%0,%1,%2,%3}, [%4];"
        : "=r"(r[0]), "=r"(r[1]), "=r"(r[2]), "=r"(r[3]) : "r"(addr));
}
__device__ __forceinline__ void mma16(float* c, const uint32_t* a, const uint32_t* b) {
    asm volatile("mma.sync.aligned.m16n8k16.row.col.f32.f16.f16.f32 "
        "{%0,%1,%2,%3}, {%4,%5,%6,%7}, {%8,%9}, {%0,%1,%2,%3};"
        : "+f"(c[0]), "+f"(c[1]), "+f"(c[2]), "+f"(c[3])
        : "r"(a[0]), "r"(a[1]), "r"(a[2]), "r"(a[3]), "r"(b[0]), "r"(b[1]));
}
__device__ __forceinline__ uint32_t f2h2(float a, float b) {
    __half2 h = __floats2half2_rn(a, b);
    return *(uint32_t*)&h;
}

// ---------------- combined prep: all W transposes + pos-tail + out zero ----------------
__global__ void prep_all(const float* __restrict__ W1, const float* __restrict__ W2,
                         const float* __restrict__ W3,
                         __half* __restrict__ w1t, __half* __restrict__ w2t,
                         __half* __restrict__ w3t, float* __restrict__ w1tail,
                         float* __restrict__ out) {
    int i = blockIdx.x * blockDim.x + threadIdx.x;
    if (i < 32 * 1024) out[i] = 0.0f;
    if (i < 768) w1tail[i] = W1[65536 + i];                 // rows 256..258 of [259,256]
    if (i < 256 * 256) {
        int n = i >> 8, k = i & 255;
        w1t[i] = __float2half_rn(W1[(size_t)k * 256 + n]);
    }
    if (i < 512 * 256) {
        int n = i >> 8, k = i & 255;
        w2t[i] = __float2half_rn(W2[(size_t)k * 512 + n]);
    }
    if (i < 1024 * 512) {
        int n = i >> 9, k = i & 511;
        w3t[i] = __float2half_rn(W3[(size_t)k * 1024 + n]);
    }
}

// ---------------- fused GEMM: C = relu(A @ B + bias [+ pos tail]) ----------------
// MODE 0: A fp16 cp.async; store fp16 (L2)
// MODE 1: A fp16 cp.async; fused segment-max epilogue (L3)
// MODE 2: A fp32 (x), reg-prefetch + convert; epilogue adds pos@W1tail in fp32; store fp16 (L1)
template<int MODE>
__global__ __launch_bounds__(256, 2)
void tc_gemm(const void* __restrict__ Av, const __half* __restrict__ Bt,
             const float* __restrict__ bias, const float* __restrict__ pos,
             const float* __restrict__ w1tail, void* __restrict__ Cv,
             int N, int lda, int ldb, int nCh)
{
    extern __shared__ __half sh[];
    __half* As = sh;
    __half* Bs = sh + STAGES * STAGE_F;
    const uint32_t sbA = s2u(As), sbB = s2u(Bs);
    const int tid = threadIdx.x;
    const int lane = tid & 31, wid = tid >> 5;
    const int wm = (wid >> 2) * 64;
    const int wn = (wid & 3) * 32;
    const int row0 = blockIdx.y * BM, col0 = blockIdx.x * BN;

    const __half* A16 = (const __half*)Av;
    const float*  A32 = (const float*)Av;

    float acc[4][4][4];
    #pragma unroll
    for (int i = 0; i < 4; i++)
        #pragma unroll
        for (int j = 0; j < 4; j++)
            #pragma unroll
            for (int k = 0; k < 4; k++) acc[i][j][k] = 0.0f;

    const int a_row = ((lane >> 3) & 1) * 8 + (lane & 7);
    const int a_col = ((lane >> 4) & 1) * 8;
    const int b_row = ((lane >> 4) & 1) * 8 + (lane & 7);
    const int b_col = ((lane >> 3) & 1) * 8;

    float4 aPre[8];                      // MODE 2 prefetch regs (128x64 f32 / 256 thr = 8 f4)

    auto loadB = [&](int kc, int s) {
        const int kb = kc * BK;
        #pragma unroll
        for (int i = 0; i < 4; i++) {
            int idx = i * 256 + tid;
            int r = idx >> 3, c8 = idx & 7;
            cp16(sbB + (s * STAGE_F + r * PITCH + c8 * 8) * 2,
                 &Bt[(size_t)(col0 + r) * ldb + kb + c8 * 8]);
        }
    };
    auto loadA16 = [&](int kc, int s) {
        const int kb = kc * BK;
        #pragma unroll
        for (int i = 0; i < 4; i++) {
            int idx = i * 256 + tid;
            int r = idx >> 3, c8 = idx & 7;
            cp16(sbA + (s * STAGE_F + r * PITCH + c8 * 8) * 2,
                 &A16[(size_t)(row0 + r) * lda + kb + c8 * 8]);
        }
    };
    auto ldA32 = [&](int kc) {           // MODE 2: fp32 x -> regs
        const int kb = kc * BK;
        #pragma unroll
        for (int i = 0; i < 8; i++) {
            int idx = i * 256 + tid;
            int r = idx >> 4, c4 = idx & 15;
            aPre[i] = *(const float4*)&A32[(size_t)(row0 + r) * lda + kb + c4 * 4];
        }
    };
    auto stA32 = [&](int s) {            // regs -> fp16 smem (STS.64, conflict-free)
        #pragma unroll
        for (int i = 0; i < 8; i++) {
            int idx = i * 256 + tid;
            int r = idx >> 4, c4 = idx & 15;
            *(uint2*)((char*)As + (size_t)(s * STAGE_F + r * PITCH + c4 * 4) * 2) =
                make_uint2(f2h2(aPre[i].x, aPre[i].y), f2h2(aPre[i].z, aPre[i].w));
        }
    };

    // ---- prologue ----
    if (MODE == 2) {
        ldA32(0); loadB(0, 0);
        asm volatile("cp.async.commit_group;" ::: "memory");
        stA32(0);
        ldA32(1); loadB(1, 1);
        asm volatile("cp.async.commit_group;" ::: "memory");
        stA32(1);
    } else {
        loadA16(0, 0); loadB(0, 0);
        asm volatile("cp.async.commit_group;" ::: "memory");
        loadA16(1, 1); loadB(1, 1);
        asm volatile("cp.async.commit_group;" ::: "memory");
    }

    for (int kc = 0; kc < nCh; kc++) {
        if (kc + 1 < nCh) asm volatile("cp.async.wait_group 1;" ::: "memory");
        else              asm volatile("cp.async.wait_group 0;" ::: "memory");
        __syncthreads();
        const bool pf = (kc + 2 < nCh);
        if (pf) {
            const int ns = (kc + 2) % STAGES;
            if (MODE == 2) { loadB(kc + 2, ns); ldA32(kc + 2); }
            else           { loadA16(kc + 2, ns); loadB(kc + 2, ns); }
            asm volatile("cp.async.commit_group;" ::: "memory");
        }

        const uint32_t aBase = sbA + ((kc % STAGES) * STAGE_F) * 2;
        const uint32_t bBase = sbB + ((kc % STAGES) * STAGE_F) * 2;
        #pragma unroll
        for (int kq = 0; kq < 4; kq++) {
            const int k0 = kq * 16;
            uint32_t af[4][4], bf[4][2];
            #pragma unroll
            for (int im = 0; im < 4; im++)
                ldsm4(af[im], aBase + ((wm + im * 16 + a_row) * PITCH + a_col + k0) * 2);
            #pragma unroll
            for (int ip = 0; ip < 2; ip++) {
                uint32_t t[4];
                ldsm4(t, bBase + ((wn + ip * 16 + b_row) * PITCH + b_col + k0) * 2);
                bf[ip * 2][0] = t[0]; bf[ip * 2][1] = t[1];
                bf[ip * 2 + 1][0] = t[2]; bf[ip * 2 + 1][1] = t[3];
            }
            #pragma unroll
            for (int im = 0; im < 4; im++)
                #pragma unroll
                for (int in = 0; in < 4; in++)
                    mma16(acc[im][in], af[im], bf[in]);
        }
        if (MODE == 2 && pf) stA32((kc + 2) % STAGES);   // buffer (kc-1)%3, free since sync
    }

    // ---- epilogue ----
    if (MODE != 1) {
        __half* C = (__half*)Cv;
        float pr[4][2][3];                     // MODE 2: pos for this thread's 8 rows
        if (MODE == 2) {
            #pragma unroll
            for (int im = 0; im < 4; im++)
                #pragma unroll
                for (int h = 0; h < 2; h++) {
                    const int r1 = row0 + wm + im * 16 + (lane >> 2) + h * 8;
                    pr[im][h][0] = pos[(size_t)r1 * 3 + 0];
                    pr[im][h][1] = pos[(size_t)r1 * 3 + 1];
                    pr[im][h][2] = pos[(size_t)r1 * 3 + 2];
                }
        }
        #pragma unroll
        for (int in = 0; in < 4; in++) {
            const int c = col0 + wn + in * 8 + (lane & 3) * 2;
            const float b0 = bias[c], b1 = bias[c + 1];
            float t00 = 0, t01 = 0, t10 = 0, t11 = 0, t20 = 0, t21 = 0;
            if (MODE == 2) {
                t00 = w1tail[c];       t01 = w1tail[c + 1];
                t10 = w1tail[256 + c]; t11 = w1tail[256 + c + 1];
                t20 = w1tail[512 + c]; t21 = w1tail[512 + c + 1];
            }
            #pragma unroll
            for (int im = 0; im < 4; im++) {
                const int r1 = row0 + wm + im * 16 + (lane >> 2);
                float v[2][2];
                #pragma unroll
                for (int h = 0; h < 2; h++) {
                    float e0 = acc[im][in][h * 2 + 0] + b0;
                    float e1 = acc[im][in][h * 2 + 1] + b1;
                    if (MODE == 2) {
                        e0 += pr[im][h][0] * t00 + pr[im][h][1] * t10 + pr[im][h][2] * t20;
                        e1 += pr[im][h][0] * t01 + pr[im][h][1] * t11 + pr[im][h][2] * t21;
                    }
                    v[h][0] = fmaxf(e0, 0.f); v[h][1] = fmaxf(e1, 0.f);
                }
                *(__half2*)&C[(size_t)r1 * N + c] =
                    __halves2half2(__float2half_rn(v[0][0]), __float2half_rn(v[0][1]));
                *(__half2*)&C[(size_t)(r1 + 8) * N + c] =
                    __halves2half2(__float2half_rn(v[1][0]), __float2half_rn(v[1][1]));
            }
        }
    } else {
        float* C = (float*)Cv;
        __syncthreads();
        int* smax = (int*)sh;
        if (tid < 128) smax[tid] = 0;
        __syncthreads();
        #pragma unroll
        for (int in = 0; in < 4; in++) {
            const int c = col0 + wn + in * 8 + (lane & 3) * 2;
            const float b0 = bias[c], b1 = bias[c + 1];
            #pragma unroll
            for (int p = 0; p < 2; p++) {
                float m = fmaxf(acc[0][in][p], acc[0][in][p + 2]);
                #pragma unroll
                for (int im = 1; im < 4; im++)
                    m = fmaxf(m, fmaxf(acc[im][in][p], acc[im][in][p + 2]));
                m = fmaxf(m + (p ? b1 : b0), 0.f);
                m = fmaxf(m, __shfl_xor_sync(0xFFFFFFFFu, m, 4));
                m = fmaxf(m, __shfl_xor_sync(0xFFFFFFFFu, m, 8));
                m = fmaxf(m, __shfl_xor_sync(0xFFFFFFFFu, m, 16));
                if ((lane >> 2) == 0)
                    atomicMax(&smax[wn + in * 8 + (lane & 3) * 2 + p], __float_as_int(m));
            }
        }
        __syncthreads();
        if (tid < 128) {
            const int seg = row0 >> 12;
            atomicMax((int*)&C[(size_t)seg * N + col0 + tid], smax[tid]);
        }
    }
}

// ---------------- launch ----------------
extern "C" void kernel_launch(void* const* d_in, const int* in_sizes, int n_in,
                              void* d_out, int out_size) {
    const float* x   = (const float*)d_in[0];
    const float* pos = (const float*)d_in[1];
    const float* W1  = (const float*)d_in[3];
    const float* b1  = (const float*)d_in[4];
    const float* W2  = (const float*)d_in[5];
    const float* b2  = (const float*)d_in[6];
    const float* W3  = (const float*)d_in[7];
    const float* b3  = (const float*)d_in[8];
    float* out = (float*)d_out;

    __half *h1, *h2, *w1t, *w2t, *w3t;
    float* w1tail;
    cudaGetSymbolAddress((void**)&h1,  g_h1);
    cudaGetSymbolAddress((void**)&h2,  g_h2);
    cudaGetSymbolAddress((void**)&w1t, g_w1t);
    cudaGetSymbolAddress((void**)&w2t, g_w2t);
    cudaGetSymbolAddress((void**)&w3t, g_w3t);
    cudaGetSymbolAddress((void**)&w1tail, g_w1tail);

    cudaFuncSetAttribute(tc_gemm<0>, cudaFuncAttributeMaxDynamicSharedMemorySize, SMEM_BYTES);
    cudaFuncSetAttribute(tc_gemm<1>, cudaFuncAttributeMaxDynamicSharedMemorySize, SMEM_BYTES);
    cudaFuncSetAttribute(tc_gemm<2>, cudaFuncAttributeMaxDynamicSharedMemorySize, SMEM_BYTES);

    prep_all<<<(1024 * 512 + 255) / 256, 256>>>(W1, W2, W3, w1t, w2t, w3t, w1tail, out);

    // L1: x[131072,256] @ W1t[256,256] + pos tail -> h1 (fp16)
    tc_gemm<2><<<dim3(2, MPTS / BM), 256, SMEM_BYTES>>>(x, w1t, b1, pos, w1tail, h1,
                                                        256, 256, 256, 4);
    // L2: h1 @ W2t[512,256] -> h2 (fp16)
    tc_gemm<0><<<dim3(4, MPTS / BM), 256, SMEM_BYTES>>>(h1, w2t, b2, nullptr, nullptr, h2,
                                                        512, 256, 256, 4);
    // L3: h2 @ W3t[1024,512] -> fused segment max -> out[32,1024] f32
    tc_gemm<1><<<dim3(8, MPTS / BM), 256, SMEM_BYTES>>>(h2, w3t, b3, nullptr, nullptr, out,
                                                        1024, 512, 512, 8);
}

// round 12
// speedup vs baseline: 1.5230x; 1.5230x over previous
#include <cuda_runtime.h>
#include <cuda_fp16.h>
#include <cstdint>

#define MPTS 131072
#define BM 128
#define BN 128
#define BK 64                       // halves per k-chunk
#define STAGES 3
#define PITCH 72                    // smem row pitch in halves: 144B = 9*16B (odd) -> conflict-free
#define STAGE_F (128 * PITCH)       // halves per tile
#define SMEM_BYTES (STAGES * 2 * STAGE_F * 2)   // 110592 B

// ---- scratch (device globals; no allocation allowed) ----
__device__ __half g_xh[(size_t)MPTS * 256];   // x cast to fp16 (contiguous, no padding)
__device__ __half g_h1[(size_t)MPTS * 256];
__device__ __half g_h2[(size_t)MPTS * 512];
__device__ __half g_w1t[256 * 256];           // W1[0:256]^T  [N][K] fp16
__device__ __half g_w2t[512 * 256];
__device__ __half g_w3t[1024 * 512];
__device__ float  g_w1tail[3 * 256];          // W1[256:259][:] fp32 (pos tail, rank-3)

// ---------------- helpers ----------------
__device__ __forceinline__ uint32_t s2u(const void* p) {
    uint32_t a;
    asm("{ .reg .u64 t; cvta.to.shared.u64 t, %1; cvt.u32.u64 %0, t; }" : "=r"(a) : "l"(p));
    return a;
}
__device__ __forceinline__ void cp16(uint32_t dst, const void* src) {
    asm volatile("cp.async.cg.shared.global [%0], [%1], 16;" :: "r"(dst), "l"(src));
}
__device__ __forceinline__ void ldsm4(uint32_t* r, uint32_t addr) {
    asm volatile("ldmatrix.sync.aligned.m8n8.x4.shared.b16 {%0,%1,%2,%3}, [%4];"
        : "=r"(r[0]), "=r"(r[1]), "=r"(r[2]), "=r"(r[3]) : "r"(addr));
}
__device__ __forceinline__ void mma16(float* c, const uint32_t* a, const uint32_t* b) {
    asm volatile("mma.sync.aligned.m16n8k16.row.col.f32.f16.f16.f32 "
        "{%0,%1,%2,%3}, {%4,%5,%6,%7}, {%8,%9}, {%0,%1,%2,%3};"
        : "+f"(c[0]), "+f"(c[1]), "+f"(c[2]), "+f"(c[3])
        : "r"(a[0]), "r"(a[1]), "r"(a[2]), "r"(a[3]), "r"(b[0]), "r"(b[1]));
}

// ---------------- prep kernels ----------------
// x is [MPTS,256] row-major contiguous -> pure vectorized fp32->fp16 cast
__global__ void prep_x(const float* __restrict__ x, __half* __restrict__ xh) {
    int i = (blockIdx.x * blockDim.x + threadIdx.x) * 4;
    float4 v = *(const float4*)&x[i];
    __half2 a = __floats2half2_rn(v.x, v.y), b = __floats2half2_rn(v.z, v.w);
    *(uint2*)&xh[i] = make_uint2(*(uint32_t*)&a, *(uint32_t*)&b);
}
// all W transposes + pos-tail + out zero in one launch
__global__ void prep_w(const float* __restrict__ W1, const float* __restrict__ W2,
                       const float* __restrict__ W3,
                       __half* __restrict__ w1t, __half* __restrict__ w2t,
                       __half* __restrict__ w3t, float* __restrict__ w1tail,
                       float* __restrict__ out) {
    int i = blockIdx.x * blockDim.x + threadIdx.x;
    if (i < 32 * 1024) out[i] = 0.0f;
    if (i < 768) w1tail[i] = W1[65536 + i];                 // rows 256..258 of [259,256]
    if (i < 256 * 256) {
        int n = i >> 8, k = i & 255;
        w1t[i] = __float2half_rn(W1[(size_t)k * 256 + n]);
    }
    if (i < 512 * 256) {
        int n = i >> 8, k = i & 255;
        w2t[i] = __float2half_rn(W2[(size_t)k * 512 + n]);
    }
    if (i < 1024 * 512) {
        int n = i >> 9, k = i & 511;
        w3t[i] = __float2half_rn(W3[(size_t)k * 1024 + n]);
    }
}

// ---------------- fused GEMM: C = relu(A @ B + bias [+ pos@W1tail]) ----------------
// Round-8 mainloop (known good). SEGMAX: fused segment-max epilogue (L3).
// TAIL: add fp32 rank-3 pos contribution in epilogue (L1).
template<int SEGMAX, int TAIL>
__global__ __launch_bounds__(256, 2)
void tc_gemm(const __half* __restrict__ A, const __half* __restrict__ Bt,
             const float* __restrict__ bias, const float* __restrict__ pos,
             const float* __restrict__ w1tail, void* __restrict__ Cv,
             int N, int lda, int ldb, int nCh)
{
    extern __shared__ __half sh[];
    __half* As = sh;
    __half* Bs = sh + STAGES * STAGE_F;
    const uint32_t sbA = s2u(As), sbB = s2u(Bs);
    const int tid = threadIdx.x;
    const int lane = tid & 31, wid = tid >> 5;
    const int wm = (wid >> 2) * 64;
    const int wn = (wid & 3) * 32;
    const int row0 = blockIdx.y * BM, col0 = blockIdx.x * BN;

    float acc[4][4][4];
    #pragma unroll
    for (int i = 0; i < 4; i++)
        #pragma unroll
        for (int j = 0; j < 4; j++)
            #pragma unroll
            for (int k = 0; k < 4; k++) acc[i][j][k] = 0.0f;

    const int a_row = ((lane >> 3) & 1) * 8 + (lane & 7);
    const int a_col = ((lane >> 4) & 1) * 8;
    const int b_row = ((lane >> 4) & 1) * 8 + (lane & 7);
    const int b_col = ((lane >> 3) & 1) * 8;

    auto load_stage = [&](int kc, int s) {
        const int kb = kc * BK;
        #pragma unroll
        for (int i = 0; i < 4; i++) {          // A: 128 rows x 8 chunks of 16B
            int idx = i * 256 + tid;
            int r = idx >> 3, c8 = idx & 7;
            cp16(sbA + (s * STAGE_F + r * PITCH + c8 * 8) * 2,
                 &A[(size_t)(row0 + r) * lda + kb + c8 * 8]);
        }
        #pragma unroll
        for (int i = 0; i < 4; i++) {          // B: 128 n-rows x 8 chunks
            int idx = i * 256 + tid;
            int r = idx >> 3, c8 = idx & 7;
            cp16(sbB + (s * STAGE_F + r * PITCH + c8 * 8) * 2,
                 &Bt[(size_t)(col0 + r) * ldb + kb + c8 * 8]);
        }
        asm volatile("cp.async.commit_group;" ::: "memory");
    };

    load_stage(0, 0);
    load_stage(1, 1);

    for (int kc = 0; kc < nCh; kc++) {
        if (kc + 1 < nCh) asm volatile("cp.async.wait_group 1;" ::: "memory");
        else              asm volatile("cp.async.wait_group 0;" ::: "memory");
        __syncthreads();
        if (kc + 2 < nCh) load_stage(kc + 2, (kc + 2) % STAGES);

        const uint32_t aBase = sbA + ((kc % STAGES) * STAGE_F) * 2;
        const uint32_t bBase = sbB + ((kc % STAGES) * STAGE_F) * 2;
        #pragma unroll
        for (int kq = 0; kq < 4; kq++) {
            const int k0 = kq * 16;
            uint32_t af[4][4], bf[4][2];
            #pragma unroll
            for (int im = 0; im < 4; im++)
                ldsm4(af[im], aBase + ((wm + im * 16 + a_row) * PITCH + a_col + k0) * 2);
            #pragma unroll
            for (int ip = 0; ip < 2; ip++) {
                uint32_t t[4];
                ldsm4(t, bBase + ((wn + ip * 16 + b_row) * PITCH + b_col + k0) * 2);
                bf[ip * 2][0] = t[0]; bf[ip * 2][1] = t[1];
                bf[ip * 2 + 1][0] = t[2]; bf[ip * 2 + 1][1] = t[3];
            }
            #pragma unroll
            for (int im = 0; im < 4; im++)
                #pragma unroll
                for (int in = 0; in < 4; in++)
                    mma16(acc[im][in], af[im], bf[in]);
        }
    }

    // ---- epilogue ----
    if (!SEGMAX) {
        __half* C = (__half*)Cv;
        float pr[4][2][3];                     // TAIL: pos for this thread's 8 rows
        if (TAIL) {
            #pragma unroll
            for (int im = 0; im < 4; im++)
                #pragma unroll
                for (int h = 0; h < 2; h++) {
                    const int r1 = row0 + wm + im * 16 + (lane >> 2) + h * 8;
                    pr[im][h][0] = pos[(size_t)r1 * 3 + 0];
                    pr[im][h][1] = pos[(size_t)r1 * 3 + 1];
                    pr[im][h][2] = pos[(size_t)r1 * 3 + 2];
                }
        }
        #pragma unroll
        for (int in = 0; in < 4; in++) {
            const int c = col0 + wn + in * 8 + (lane & 3) * 2;
            const float b0 = bias[c], b1 = bias[c + 1];
            float t00 = 0, t01 = 0, t10 = 0, t11 = 0, t20 = 0, t21 = 0;
            if (TAIL) {
                t00 = w1tail[c];       t01 = w1tail[c + 1];
                t10 = w1tail[256 + c]; t11 = w1tail[256 + c + 1];
                t20 = w1tail[512 + c]; t21 = w1tail[512 + c + 1];
            }
            #pragma unroll
            for (int im = 0; im < 4; im++) {
                const int r1 = row0 + wm + im * 16 + (lane >> 2);
                float v[2][2];
                #pragma unroll
                for (int h = 0; h < 2; h++) {
                    float e0 = acc[im][in][h * 2 + 0] + b0;
                    float e1 = acc[im][in][h * 2 + 1] + b1;
                    if (TAIL) {
                        e0 += pr[im][h][0] * t00 + pr[im][h][1] * t10 + pr[im][h][2] * t20;
                        e1 += pr[im][h][0] * t01 + pr[im][h][1] * t11 + pr[im][h][2] * t21;
                    }
                    v[h][0] = fmaxf(e0, 0.f); v[h][1] = fmaxf(e1, 0.f);
                }
                *(__half2*)&C[(size_t)r1 * N + c] =
                    __halves2half2(__float2half_rn(v[0][0]), __float2half_rn(v[0][1]));
                *(__half2*)&C[(size_t)(r1 + 8) * N + c] =
                    __halves2half2(__float2half_rn(v[1][0]), __float2half_rn(v[1][1]));
            }
        }
    } else {
        float* C = (float*)Cv;
        __syncthreads();                       // done reading smem tiles
        int* smax = (int*)sh;                  // reuse smem: 128 ints
        if (tid < 128) smax[tid] = 0;
        __syncthreads();
        #pragma unroll
        for (int in = 0; in < 4; in++) {
            const int c = col0 + wn + in * 8 + (lane & 3) * 2;
            const float b0 = bias[c], b1 = bias[c + 1];
            #pragma unroll
            for (int p = 0; p < 2; p++) {
                float m = fmaxf(acc[0][in][p], acc[0][in][p + 2]);
                #pragma unroll
                for (int im = 1; im < 4; im++)
                    m = fmaxf(m, fmaxf(acc[im][in][p], acc[im][in][p + 2]));
                m = fmaxf(m + (p ? b1 : b0), 0.f);
                m = fmaxf(m, __shfl_xor_sync(0xFFFFFFFFu, m, 4));
                m = fmaxf(m, __shfl_xor_sync(0xFFFFFFFFu, m, 8));
                m = fmaxf(m, __shfl_xor_sync(0xFFFFFFFFu, m, 16));
                if ((lane >> 2) == 0)
                    atomicMax(&smax[wn + in * 8 + (lane & 3) * 2 + p], __float_as_int(m));
            }
        }
        __syncthreads();
        if (tid < 128) {
            const int seg = row0 >> 12;       // 4096 rows per segment
            atomicMax((int*)&C[(size_t)seg * N + col0 + tid], smax[tid]);
        }
    }
}

// ---------------- launch ----------------
extern "C" void kernel_launch(void* const* d_in, const int* in_sizes, int n_in,
                              void* d_out, int out_size) {
    const float* x   = (const float*)d_in[0];
    const float* pos = (const float*)d_in[1];
    const float* W1  = (const float*)d_in[3];
    const float* b1  = (const float*)d_in[4];
    const float* W2  = (const float*)d_in[5];
    const float* b2  = (const float*)d_in[6];
    const float* W3  = (const float*)d_in[7];
    const float* b3  = (const float*)d_in[8];
    float* out = (float*)d_out;

    __half *xh, *h1, *h2, *w1t, *w2t, *w3t;
    float* w1tail;
    cudaGetSymbolAddress((void**)&xh,  g_xh);
    cudaGetSymbolAddress((void**)&h1,  g_h1);
    cudaGetSymbolAddress((void**)&h2,  g_h2);
    cudaGetSymbolAddress((void**)&w1t, g_w1t);
    cudaGetSymbolAddress((void**)&w2t, g_w2t);
    cudaGetSymbolAddress((void**)&w3t, g_w3t);
    cudaGetSymbolAddress((void**)&w1tail, g_w1tail);

    cudaFuncSetAttribute((tc_gemm<0,1>), cudaFuncAttributeMaxDynamicSharedMemorySize, SMEM_BYTES);
    cudaFuncSetAttribute((tc_gemm<0,0>), cudaFuncAttributeMaxDynamicSharedMemorySize, SMEM_BYTES);
    cudaFuncSetAttribute((tc_gemm<1,0>), cudaFuncAttributeMaxDynamicSharedMemorySize, SMEM_BYTES);

    prep_x<<<(MPTS * 256) / 1024, 256>>>(x, xh);
    prep_w<<<(1024 * 512 + 255) / 256, 256>>>(W1, W2, W3, w1t, w2t, w3t, w1tail, out);

    // L1: xh[131072,256] @ W1t[256,256] + pos tail -> h1 (fp16)
    tc_gemm<0,1><<<dim3(2, MPTS / BM), 256, SMEM_BYTES>>>(xh, w1t, b1, pos, w1tail, h1,
                                                          256, 256, 256, 4);
    // L2: h1 @ W2t[512,256] -> h2 (fp16)
    tc_gemm<0,0><<<dim3(4, MPTS / BM), 256, SMEM_BYTES>>>(h1, w2t, b2, nullptr, nullptr, h2,
                                                          512, 256, 256, 4);
    // L3: h2 @ W3t[1024,512] -> fused segment max -> out[32,1024] f32
    tc_gemm<1,0><<<dim3(8, MPTS / BM), 256, SMEM_BYTES>>>(h2, w3t, b3, nullptr, nullptr, out,
                                                          1024, 512, 512, 8);
}